// round 1
// baseline (speedup 1.0000x reference)
#include <cuda_runtime.h>

#define NN 100000
#define DD 128
#define HH 64
#define KK 8
#define LL 3
#define CC 16
#define EE 1600000

// Scratch (allocation-free rule: __device__ globals)
__device__ __align__(128) float g_h[NN * HH];
__device__ __align__(128) float g_agg[NN * HH];
__device__ __align__(128) float g_val[EE];
__device__ __align__(128) float g_dn[NN];

// ---------------- utility kernels ----------------
__global__ void zero_dn_kernel() {
    int i = blockIdx.x * blockDim.x + threadIdx.x;
    if (i < NN) g_dn[i] = 0.f;
}

__global__ void deg_kernel(const int* __restrict__ col) {
    int e = blockIdx.x * blockDim.x + threadIdx.x;
    if (e < EE) atomicAdd(&g_dn[col[e]], 1.f);
}

__global__ void dn_kernel() {
    int i = blockIdx.x * blockDim.x + threadIdx.x;
    if (i < NN) {
        float d = g_dn[i];
        g_dn[i] = d > 0.f ? rsqrtf(d) : 0.f;
    }
}

__global__ void val_kernel(const int* __restrict__ row, const int* __restrict__ col) {
    int e = blockIdx.x * blockDim.x + threadIdx.x;
    if (e < EE) g_val[e] = g_dn[row[e]] * g_dn[col[e]];
}

__global__ void zero_agg_kernel() {
    int i = blockIdx.x * blockDim.x + threadIdx.x;
    if (i < NN * HH / 4) reinterpret_cast<float4*>(g_agg)[i] = make_float4(0.f, 0.f, 0.f, 0.f);
}

// ---------------- fc0: h = relu(x @ w + b) ----------------
// 64 nodes x 64 outputs per block, 256 threads, 4x4 per thread.
__global__ void __launch_bounds__(256) fc0_kernel(const float* __restrict__ x,
                                                  const float* __restrict__ w,
                                                  const float* __restrict__ b) {
    extern __shared__ float sm[];
    float* s_x = sm;               // 64 x 132 (padded)
    float* s_w = sm + 64 * 132;    // 128 x 64

    int n0 = blockIdx.x * 64;
    int t = threadIdx.x;

    for (int idx = t; idx < 64 * 128; idx += 256) {
        int n = idx >> 7, f = idx & 127;
        int gn = n0 + n;
        s_x[n * 132 + f] = (gn < NN) ? x[gn * 128 + f] : 0.f;
    }
    for (int idx = t; idx < 128 * 64; idx += 256) s_w[idx] = w[idx];
    __syncthreads();

    int ty = t >> 4, tx = t & 15;
    int r0 = ty * 4, c0 = tx * 4;
    float acc[4][4] = {};

#pragma unroll 4
    for (int f = 0; f < 128; f++) {
        float a[4];
#pragma unroll
        for (int i = 0; i < 4; i++) a[i] = s_x[(r0 + i) * 132 + f];
        float4 b4 = *reinterpret_cast<const float4*>(&s_w[f * 64 + c0]);
#pragma unroll
        for (int i = 0; i < 4; i++) {
            acc[i][0] += a[i] * b4.x;
            acc[i][1] += a[i] * b4.y;
            acc[i][2] += a[i] * b4.z;
            acc[i][3] += a[i] * b4.w;
        }
    }

    float4 bias = *reinterpret_cast<const float4*>(&b[c0]);
#pragma unroll
    for (int i = 0; i < 4; i++) {
        int gn = n0 + r0 + i;
        if (gn < NN) {
            float4 o;
            o.x = fmaxf(acc[i][0] + bias.x, 0.f);
            o.y = fmaxf(acc[i][1] + bias.y, 0.f);
            o.z = fmaxf(acc[i][2] + bias.z, 0.f);
            o.w = fmaxf(acc[i][3] + bias.w, 0.f);
            *reinterpret_cast<float4*>(&g_h[gn * 64 + c0]) = o;
        }
    }
}

// ---------------- edge scatter: agg[col] += val * h[row] ----------------
// 16 lanes per edge, float4 gather + red.global.add.v4.f32 scatter.
__global__ void __launch_bounds__(256) scatter_kernel(const int* __restrict__ row,
                                                      const int* __restrict__ col) {
    unsigned idx = blockIdx.x * 256u + threadIdx.x;
    unsigned e = idx >> 4;
    unsigned q = idx & 15u;
    if (e < EE) {
        int r = row[e];
        int c = col[e];
        float v = g_val[e];
        float4 hv = *reinterpret_cast<const float4*>(&g_h[r * 64 + q * 4]);
        float* p = &g_agg[c * 64 + q * 4];
        asm volatile("red.global.add.v4.f32 [%0], {%1, %2, %3, %4};"
                     :: "l"(p), "f"(hv.x * v), "f"(hv.y * v), "f"(hv.z * v), "f"(hv.w * v)
                     : "memory");
    }
}

// ---------------- conv layer: gating + einsum + residual + relu, in-place h ----------------
// Per block: 64 nodes, all 64 outputs. hi = [agg || h] in smem (64x132 padded).
// Gating (h_env==0 so only first H rows of env_w matter) computed in smem,
// then 8 sequential 128x64 W panels with e-weighted combine.
__global__ void __launch_bounds__(256) conv_kernel(const float* __restrict__ cw,
                                                   const float* __restrict__ ew,
                                                   const float* __restrict__ eb) {
    extern __shared__ float sm[];
    float* s_hi = sm;                 // 64 x 132
    float* s_w  = sm + 64 * 132;      // 128 x 64
    float* s_e  = s_w + 128 * 64;     // 64 x 8
    float* s_ew = s_e + 512;          // 64 x 8

    int n0 = blockIdx.x * 64;
    int t = threadIdx.x;

    for (int idx = t; idx < 64 * 128; idx += 256) {
        int n = idx >> 7, f = idx & 127;
        int gn = n0 + n;
        float v = 0.f;
        if (gn < NN) v = (f < 64) ? g_agg[gn * 64 + f] : g_h[gn * 64 + (f - 64)];
        s_hi[n * 132 + f] = v;
    }
    for (int idx = t; idx < 512; idx += 256) s_ew[idx] = ew[idx];
    __syncthreads();

    // gating logits: logit[n][k] = h[n,:] @ env_w[:64,k] + env_b[k]
    for (int p = t; p < 512; p += 256) {
        int n = p >> 3, k = p & 7;
        float s = eb[k];
#pragma unroll 8
        for (int f = 0; f < 64; f++) s += s_hi[n * 132 + 64 + f] * s_ew[f * 8 + k];
        s_e[p] = s;
    }
    __syncthreads();
    // softmax + threshold: e = pi * (pi > 0.1)
    if (t < 64) {
        float l[8];
        float m = -1e30f;
#pragma unroll
        for (int k = 0; k < 8; k++) { l[k] = s_e[t * 8 + k]; m = fmaxf(m, l[k]); }
        float sum = 0.f;
#pragma unroll
        for (int k = 0; k < 8; k++) { l[k] = expf(l[k] - m); sum += l[k]; }
        float inv = 1.f / sum;
#pragma unroll
        for (int k = 0; k < 8; k++) {
            float pi = l[k] * inv;
            s_e[t * 8 + k] = (pi > 0.1f) ? pi : 0.f;
        }
    }

    int ty = t >> 4, tx = t & 15;
    int r0 = ty * 4, c0 = tx * 4;
    float acc[4][4] = {};

    for (int k = 0; k < KK; k++) {
        __syncthreads();  // protect s_w reuse + (first iter) s_e publish
        for (int idx = t; idx < 8192; idx += 256) s_w[idx] = cw[k * 8192 + idx];
        __syncthreads();

        float pr[4][4] = {};
#pragma unroll 4
        for (int f = 0; f < 128; f++) {
            float a[4];
#pragma unroll
            for (int i = 0; i < 4; i++) a[i] = s_hi[(r0 + i) * 132 + f];
            float4 b4 = *reinterpret_cast<const float4*>(&s_w[f * 64 + c0]);
#pragma unroll
            for (int i = 0; i < 4; i++) {
                pr[i][0] += a[i] * b4.x;
                pr[i][1] += a[i] * b4.y;
                pr[i][2] += a[i] * b4.z;
                pr[i][3] += a[i] * b4.w;
            }
        }
#pragma unroll
        for (int i = 0; i < 4; i++) {
            float ei = s_e[(r0 + i) * 8 + k];
            acc[i][0] += ei * pr[i][0];
            acc[i][1] += ei * pr[i][1];
            acc[i][2] += ei * pr[i][2];
            acc[i][3] += ei * pr[i][3];
        }
    }

    // epilogue: h = relu(out + h), in-place (block owns its rows)
#pragma unroll
    for (int i = 0; i < 4; i++) {
        int gn = n0 + r0 + i;
        if (gn < NN) {
            float4 o;
            o.x = fmaxf(acc[i][0] + s_hi[(r0 + i) * 132 + 64 + c0 + 0], 0.f);
            o.y = fmaxf(acc[i][1] + s_hi[(r0 + i) * 132 + 64 + c0 + 1], 0.f);
            o.z = fmaxf(acc[i][2] + s_hi[(r0 + i) * 132 + 64 + c0 + 2], 0.f);
            o.w = fmaxf(acc[i][3] + s_hi[(r0 + i) * 132 + 64 + c0 + 3], 0.f);
            *reinterpret_cast<float4*>(&g_h[gn * 64 + c0]) = o;
        }
    }
}

// ---------------- fc1: out = h @ w + b ----------------
__global__ void __launch_bounds__(256) fc1_kernel(const float* __restrict__ w,
                                                  const float* __restrict__ b,
                                                  float* __restrict__ out) {
    __shared__ float s_w[64 * 16];
    __shared__ float s_b[16];
    int t = threadIdx.x;
    for (int idx = t; idx < 64 * 16; idx += 256) s_w[idx] = w[idx];
    if (t < 16) s_b[t] = b[t];
    __syncthreads();

    int n = blockIdx.x * 256 + t;
    if (n < NN) {
        float hr[64];
#pragma unroll
        for (int i = 0; i < 16; i++) {
            float4 v = *reinterpret_cast<const float4*>(&g_h[n * 64 + i * 4]);
            hr[4 * i + 0] = v.x; hr[4 * i + 1] = v.y; hr[4 * i + 2] = v.z; hr[4 * i + 3] = v.w;
        }
        float o[16];
#pragma unroll
        for (int c = 0; c < 16; c++) {
            float s = s_b[c];
#pragma unroll
            for (int f = 0; f < 64; f++) s += hr[f] * s_w[f * 16 + c];
            o[c] = s;
        }
#pragma unroll
        for (int i = 0; i < 4; i++) {
            *reinterpret_cast<float4*>(&out[n * 16 + i * 4]) =
                make_float4(o[4 * i], o[4 * i + 1], o[4 * i + 2], o[4 * i + 3]);
        }
    }
}

// ---------------- launch ----------------
extern "C" void kernel_launch(void* const* d_in, const int* in_sizes, int n_in,
                              void* d_out, int out_size) {
    const float* x     = (const float*)d_in[0];
    const int*   ei    = (const int*)  d_in[1];
    const float* fc0w  = (const float*)d_in[2];
    const float* fc0b  = (const float*)d_in[3];
    const float* fc1w  = (const float*)d_in[4];
    const float* fc1b  = (const float*)d_in[5];
    const float* envw  = (const float*)d_in[6];
    const float* envb  = (const float*)d_in[7];
    const float* convw = (const float*)d_in[8];
    float* out = (float*)d_out;

    const int* row = ei;
    const int* col = ei + EE;

    const int fc0_smem  = (64 * 132 + 128 * 64) * (int)sizeof(float);
    const int conv_smem = (64 * 132 + 128 * 64 + 512 + 512) * (int)sizeof(float);
    cudaFuncSetAttribute(fc0_kernel, cudaFuncAttributeMaxDynamicSharedMemorySize, fc0_smem);
    cudaFuncSetAttribute(conv_kernel, cudaFuncAttributeMaxDynamicSharedMemorySize, conv_smem);

    // edge normalization (constant across layers)
    zero_dn_kernel<<<(NN + 255) / 256, 256>>>();
    deg_kernel<<<(EE + 255) / 256, 256>>>(col);
    dn_kernel<<<(NN + 255) / 256, 256>>>();
    val_kernel<<<(EE + 255) / 256, 256>>>(row, col);

    // h = relu(x @ fc0_w + fc0_b)
    fc0_kernel<<<(NN + 63) / 64, 256, fc0_smem>>>(x, fc0w, fc0b);

    for (int i = 0; i < LL; i++) {
        zero_agg_kernel<<<(NN * HH / 4 + 255) / 256, 256>>>();
        scatter_kernel<<<(EE * 16) / 256, 256>>>(row, col);
        conv_kernel<<<(NN + 63) / 64, 256, conv_smem>>>(
            convw + i * KK * 2 * HH * HH,   // [8,128,64] slice
            envw + i * 2 * HH * KK,         // [128,8] slice (first 64 rows used)
            envb + i * KK);
    }

    fc1_kernel<<<(NN + 255) / 256, 256>>>(fc1w, fc1b, out);
}

// round 4
// speedup vs baseline: 1.8071x; 1.8071x over previous
#include <cuda_runtime.h>
#include <cuda_bf16.h>
#include <cstdint>

#define NN 100000
#define DD 128
#define HH 64
#define KK 8
#define LL 3
#define CC 16
#define EE 1600000

// ---------------- device scratch ----------------
__device__ __align__(128) float g_h[NN * HH];
__device__ __align__(128) float g_agg[NN * HH];
__device__ __align__(128) float g_val[EE];
__device__ __align__(128) float g_dn[NN];
// pre-packed B fragments: [ (l*8+k)*2 + sel ][kstep*8+ntile][lane] as uint2
__device__ __align__(128) uint2 g_wpack[48 * 2048];

// single dynamic smem symbol shared by all kernels
extern __shared__ unsigned char dyn_smem[];

__device__ __forceinline__ uint16_t bf16_bits(float v) {
    __nv_bfloat16 b = __float2bfloat16(v);
    return *reinterpret_cast<uint16_t*>(&b);
}
__device__ __forceinline__ float bf16_val(float v) {
    return __bfloat162float(__float2bfloat16(v));
}
__device__ __forceinline__ uint32_t pack2(uint16_t lo, uint16_t hi) {
    return (uint32_t)lo | ((uint32_t)hi << 16);
}

// mma.sync m16n8k16 bf16 (row.col), f32 accumulate
__device__ __forceinline__ void hmma(float* d, const uint32_t* a, uint2 b) {
    asm volatile(
        "mma.sync.aligned.m16n8k16.row.col.f32.bf16.bf16.f32 "
        "{%0,%1,%2,%3}, {%4,%5,%6,%7}, {%8,%9}, {%0,%1,%2,%3};"
        : "+f"(d[0]), "+f"(d[1]), "+f"(d[2]), "+f"(d[3])
        : "r"(a[0]), "r"(a[1]), "r"(a[2]), "r"(a[3]), "r"(b.x), "r"(b.y));
}

// ---------------- utility kernels ----------------
__global__ void zero_dn_kernel() {
    int i = blockIdx.x * blockDim.x + threadIdx.x;
    if (i < NN) g_dn[i] = 0.f;
}
__global__ void deg_kernel(const int* __restrict__ col) {
    int e = blockIdx.x * blockDim.x + threadIdx.x;
    if (e < EE) atomicAdd(&g_dn[col[e]], 1.f);
}
__global__ void dn_kernel() {
    int i = blockIdx.x * blockDim.x + threadIdx.x;
    if (i < NN) { float d = g_dn[i]; g_dn[i] = d > 0.f ? rsqrtf(d) : 0.f; }
}
__global__ void val_kernel(const int* __restrict__ row, const int* __restrict__ col) {
    int e = blockIdx.x * blockDim.x + threadIdx.x;
    if (e < EE) g_val[e] = g_dn[row[e]] * g_dn[col[e]];
}
__global__ void zero_agg_kernel() {
    int i = blockIdx.x * blockDim.x + threadIdx.x;
    if (i < NN * HH / 4) reinterpret_cast<float4*>(g_agg)[i] = make_float4(0.f, 0.f, 0.f, 0.f);
}

// ---------------- W prepack: bf16 hi/lo split, HMMA B-fragment order ----------------
// B fragment m16n8k16 (16k x 8n), thread lane: tig=lane%4, gid=lane/4.
//   b0 = { B[tig*2][gid],   B[tig*2+1][gid] }
//   b1 = { B[tig*2+8][gid], B[tig*2+9][gid] }
// Here B[k][n] = W[f=k_global][o=n_global].
__global__ void wpack_kernel(const float* __restrict__ cw) {
    int img = blockIdx.x;          // 0..47
    int sel = img & 1;             // 0=hi, 1=lo
    int lk = img >> 1;             // l*8+k
    const float* w = cw + lk * 8192;          // [128 f][64 o]
    uint2* dst = g_wpack + img * 2048;
    for (int i = threadIdx.x; i < 2048; i += 256) {
        int lane = i & 31;
        int nt = (i >> 5) & 7;
        int ks = i >> 8;
        int tig = lane & 3, gid = lane >> 2;
        int n = nt * 8 + gid;
        int k0 = ks * 16 + tig * 2;
        float v0 = w[(k0 + 0) * 64 + n];
        float v1 = w[(k0 + 1) * 64 + n];
        float v2 = w[(k0 + 8) * 64 + n];
        float v3 = w[(k0 + 9) * 64 + n];
        uint16_t h0, h1, h2, h3;
        if (sel == 0) {
            h0 = bf16_bits(v0); h1 = bf16_bits(v1); h2 = bf16_bits(v2); h3 = bf16_bits(v3);
        } else {
            h0 = bf16_bits(v0 - bf16_val(v0));
            h1 = bf16_bits(v1 - bf16_val(v1));
            h2 = bf16_bits(v2 - bf16_val(v2));
            h3 = bf16_bits(v3 - bf16_val(v3));
        }
        dst[i] = make_uint2(pack2(h0, h1), pack2(h2, h3));
    }
}

// ---------------- fc0: h = relu(x @ w + b) ----------------
__global__ void __launch_bounds__(256) fc0_kernel(const float* __restrict__ x,
                                                  const float* __restrict__ w,
                                                  const float* __restrict__ b) {
    float* smf = reinterpret_cast<float*>(dyn_smem);
    float* s_x = smf;               // 64 x 132
    float* s_w = smf + 64 * 132;    // 128 x 64
    int n0 = blockIdx.x * 64;
    int t = threadIdx.x;
    for (int idx = t; idx < 64 * 128; idx += 256) {
        int n = idx >> 7, f = idx & 127;
        int gn = n0 + n;
        s_x[n * 132 + f] = (gn < NN) ? x[gn * 128 + f] : 0.f;
    }
    for (int idx = t; idx < 128 * 64; idx += 256) s_w[idx] = w[idx];
    __syncthreads();

    int ty = t >> 4, tx = t & 15;
    int r0 = ty * 4, c0 = tx * 4;
    float acc[4][4] = {};
#pragma unroll 4
    for (int f = 0; f < 128; f++) {
        float a[4];
#pragma unroll
        for (int i = 0; i < 4; i++) a[i] = s_x[(r0 + i) * 132 + f];
        float4 b4 = *reinterpret_cast<const float4*>(&s_w[f * 64 + c0]);
#pragma unroll
        for (int i = 0; i < 4; i++) {
            acc[i][0] += a[i] * b4.x; acc[i][1] += a[i] * b4.y;
            acc[i][2] += a[i] * b4.z; acc[i][3] += a[i] * b4.w;
        }
    }
    float4 bias = *reinterpret_cast<const float4*>(&b[c0]);
#pragma unroll
    for (int i = 0; i < 4; i++) {
        int gn = n0 + r0 + i;
        if (gn < NN) {
            float4 o;
            o.x = fmaxf(acc[i][0] + bias.x, 0.f);
            o.y = fmaxf(acc[i][1] + bias.y, 0.f);
            o.z = fmaxf(acc[i][2] + bias.z, 0.f);
            o.w = fmaxf(acc[i][3] + bias.w, 0.f);
            *reinterpret_cast<float4*>(&g_h[gn * 64 + c0]) = o;
        }
    }
}

// ---------------- edge scatter ----------------
__global__ void __launch_bounds__(256) scatter_kernel(const int* __restrict__ row,
                                                      const int* __restrict__ col) {
    unsigned idx = blockIdx.x * 256u + threadIdx.x;
    unsigned e = idx >> 4;
    unsigned q = idx & 15u;
    if (e < EE) {
        int r = row[e];
        int c = col[e];
        float v = g_val[e];
        float4 hv = *reinterpret_cast<const float4*>(&g_h[r * 64 + q * 4]);
        float* p = &g_agg[c * 64 + q * 4];
        asm volatile("red.global.add.v4.f32 [%0], {%1, %2, %3, %4};"
                     :: "l"(p), "f"(hv.x * v), "f"(hv.y * v), "f"(hv.z * v), "f"(hv.w * v)
                     : "memory");
    }
}

// ---------------- conv layer via mma.sync bf16x3 ----------------
// smem: Ah [128][136] bf16, Al [128][136] bf16, e [128][8] f32, ew 520 f32
#define A_STRIDE 136
#define SM_AH 0
#define SM_AL (128 * A_STRIDE * 2)
#define SM_E  (2 * 128 * A_STRIDE * 2)
#define SM_EW (SM_E + 128 * 8 * 4)
#define CONV_SMEM (SM_EW + 520 * 4)

__global__ void __launch_bounds__(256, 1) conv_mma_kernel(const float* __restrict__ ew,
                                                          const float* __restrict__ eb,
                                                          int layer) {
    unsigned char* smb = dyn_smem;
    uint16_t* Ah = reinterpret_cast<uint16_t*>(smb + SM_AH);
    uint16_t* Al = reinterpret_cast<uint16_t*>(smb + SM_AL);
    float* s_e = reinterpret_cast<float*>(smb + SM_E);
    float* s_ew = reinterpret_cast<float*>(smb + SM_EW);

    int t = threadIdx.x;
    int wid = t >> 5, lane = t & 31;
    int tig = lane & 3, gid = lane >> 2;
    int n0 = blockIdx.x * 128;

    // env weights + bias into smem
    for (int i = t; i < 520; i += 256) s_ew[i] = (i < 512) ? ew[i] : eb[i - 512];

    // ---- build A tile (bf16 hi/lo split) ----
    const float4* agg4 = reinterpret_cast<const float4*>(g_agg);
    const float4* h4 = reinterpret_cast<const float4*>(g_h);
    for (int idx = t; idx < 4096; idx += 256) {
        int r = idx >> 5, j = idx & 31;        // j: float4 index within row (0..31)
        int gn = n0 + r;
        float4 v = make_float4(0.f, 0.f, 0.f, 0.f);
        if (gn < NN) v = (j < 16) ? agg4[gn * 16 + j] : h4[gn * 16 + (j - 16)];
        uint16_t hx = bf16_bits(v.x), hy = bf16_bits(v.y);
        uint16_t hz = bf16_bits(v.z), hw = bf16_bits(v.w);
        uint16_t lx = bf16_bits(v.x - bf16_val(v.x));
        uint16_t ly = bf16_bits(v.y - bf16_val(v.y));
        uint16_t lz = bf16_bits(v.z - bf16_val(v.z));
        uint16_t lw = bf16_bits(v.w - bf16_val(v.w));
        *reinterpret_cast<uint2*>(&Ah[r * A_STRIDE + j * 4]) = make_uint2(pack2(hx, hy), pack2(hz, hw));
        *reinterpret_cast<uint2*>(&Al[r * A_STRIDE + j * 4]) = make_uint2(pack2(lx, ly), pack2(lz, lw));
    }
    __syncthreads();

    // ---- A fragments into registers (held across all heads) ----
    uint32_t ah[8][4], al[8][4];
    int fr0 = wid * 16 + gid;
#pragma unroll
    for (int s = 0; s < 8; s++) {
        int kc = s * 16 + tig * 2;
        ah[s][0] = *reinterpret_cast<const uint32_t*>(&Ah[fr0 * A_STRIDE + kc]);
        ah[s][1] = *reinterpret_cast<const uint32_t*>(&Ah[(fr0 + 8) * A_STRIDE + kc]);
        ah[s][2] = *reinterpret_cast<const uint32_t*>(&Ah[fr0 * A_STRIDE + kc + 8]);
        ah[s][3] = *reinterpret_cast<const uint32_t*>(&Ah[(fr0 + 8) * A_STRIDE + kc + 8]);
        al[s][0] = *reinterpret_cast<const uint32_t*>(&Al[fr0 * A_STRIDE + kc]);
        al[s][1] = *reinterpret_cast<const uint32_t*>(&Al[(fr0 + 8) * A_STRIDE + kc]);
        al[s][2] = *reinterpret_cast<const uint32_t*>(&Al[fr0 * A_STRIDE + kc + 8]);
        al[s][3] = *reinterpret_cast<const uint32_t*>(&Al[(fr0 + 8) * A_STRIDE + kc + 8]);
    }

    // ---- gating (threads 0..127, one node each), fp32 ----
    if (t < 128) {
        int gn = n0 + t;
        float hrow[64];
        if (gn < NN) {
#pragma unroll
            for (int i = 0; i < 16; i++) {
                float4 v = h4[gn * 16 + i];
                hrow[4 * i] = v.x; hrow[4 * i + 1] = v.y;
                hrow[4 * i + 2] = v.z; hrow[4 * i + 3] = v.w;
            }
        } else {
#pragma unroll
            for (int i = 0; i < 64; i++) hrow[i] = 0.f;
        }
        float lg[8];
#pragma unroll
        for (int k = 0; k < 8; k++) lg[k] = s_ew[512 + k];
#pragma unroll 8
        for (int f = 0; f < 64; f++) {
            float hv = hrow[f];
            float4 w0 = *reinterpret_cast<const float4*>(&s_ew[f * 8]);
            float4 w1 = *reinterpret_cast<const float4*>(&s_ew[f * 8 + 4]);
            lg[0] += hv * w0.x; lg[1] += hv * w0.y; lg[2] += hv * w0.z; lg[3] += hv * w0.w;
            lg[4] += hv * w1.x; lg[5] += hv * w1.y; lg[6] += hv * w1.z; lg[7] += hv * w1.w;
        }
        float m = -1e30f;
#pragma unroll
        for (int k = 0; k < 8; k++) m = fmaxf(m, lg[k]);
        float sum = 0.f;
#pragma unroll
        for (int k = 0; k < 8; k++) { lg[k] = expf(lg[k] - m); sum += lg[k]; }
        float inv = 1.f / sum;
#pragma unroll
        for (int k = 0; k < 8; k++) {
            float pi = lg[k] * inv;
            s_e[t * 8 + k] = (pi > 0.1f) ? pi : 0.f;
        }
    }
    __syncthreads();

    // ---- main MMA loop over 8 heads ----
    float acc[8][4];
#pragma unroll
    for (int nt = 0; nt < 8; nt++)
#pragma unroll
        for (int i = 0; i < 4; i++) acc[nt][i] = 0.f;

    const uint2* wp = g_wpack + (layer * 8) * 2 * 2048;

#pragma unroll 1
    for (int k = 0; k < 8; k++) {
        const uint2* bh = wp + (k * 2 + 0) * 2048;
        const uint2* bl = wp + (k * 2 + 1) * 2048;
        float acck[8][4];
#pragma unroll
        for (int nt = 0; nt < 8; nt++)
#pragma unroll
            for (int i = 0; i < 4; i++) acck[nt][i] = 0.f;

        // pass 1: (Ah + Al) x Bh
#pragma unroll
        for (int s = 0; s < 8; s++) {
            uint2 b[8];
#pragma unroll
            for (int nt = 0; nt < 8; nt++) b[nt] = bh[(s * 8 + nt) * 32 + lane];
#pragma unroll
            for (int nt = 0; nt < 8; nt++) hmma(acck[nt], ah[s], b[nt]);
#pragma unroll
            for (int nt = 0; nt < 8; nt++) hmma(acck[nt], al[s], b[nt]);
        }
        // pass 2: Ah x Bl
#pragma unroll
        for (int s = 0; s < 8; s++) {
            uint2 b[8];
#pragma unroll
            for (int nt = 0; nt < 8; nt++) b[nt] = bl[(s * 8 + nt) * 32 + lane];
#pragma unroll
            for (int nt = 0; nt < 8; nt++) hmma(acck[nt], ah[s], b[nt]);
        }

        float e0 = s_e[(wid * 16 + gid) * 8 + k];
        float e1 = s_e[(wid * 16 + gid + 8) * 8 + k];
#pragma unroll
        for (int nt = 0; nt < 8; nt++) {
            acc[nt][0] += e0 * acck[nt][0];
            acc[nt][1] += e0 * acck[nt][1];
            acc[nt][2] += e1 * acck[nt][2];
            acc[nt][3] += e1 * acck[nt][3];
        }
    }

    // ---- epilogue: h = relu(acc + h), in-place ----
    int gn0 = n0 + wid * 16 + gid;
    int gn1 = gn0 + 8;
#pragma unroll
    for (int nt = 0; nt < 8; nt++) {
        int c = nt * 8 + tig * 2;
        if (gn0 < NN) {
            float2 hv = *reinterpret_cast<const float2*>(&g_h[gn0 * 64 + c]);
            float2 o;
            o.x = fmaxf(acc[nt][0] + hv.x, 0.f);
            o.y = fmaxf(acc[nt][1] + hv.y, 0.f);
            *reinterpret_cast<float2*>(&g_h[gn0 * 64 + c]) = o;
        }
        if (gn1 < NN) {
            float2 hv = *reinterpret_cast<const float2*>(&g_h[gn1 * 64 + c]);
            float2 o;
            o.x = fmaxf(acc[nt][2] + hv.x, 0.f);
            o.y = fmaxf(acc[nt][3] + hv.y, 0.f);
            *reinterpret_cast<float2*>(&g_h[gn1 * 64 + c]) = o;
        }
    }
}

// ---------------- fc1 ----------------
__global__ void __launch_bounds__(256) fc1_kernel(const float* __restrict__ w,
                                                  const float* __restrict__ b,
                                                  float* __restrict__ out) {
    __shared__ float s_w[64 * 16];
    __shared__ float s_b[16];
    int t = threadIdx.x;
    for (int idx = t; idx < 64 * 16; idx += 256) s_w[idx] = w[idx];
    if (t < 16) s_b[t] = b[t];
    __syncthreads();
    int n = blockIdx.x * 256 + t;
    if (n < NN) {
        float hr[64];
#pragma unroll
        for (int i = 0; i < 16; i++) {
            float4 v = *reinterpret_cast<const float4*>(&g_h[n * 64 + i * 4]);
            hr[4 * i] = v.x; hr[4 * i + 1] = v.y; hr[4 * i + 2] = v.z; hr[4 * i + 3] = v.w;
        }
        float o[16];
#pragma unroll
        for (int c = 0; c < 16; c++) {
            float s = s_b[c];
#pragma unroll
            for (int f = 0; f < 64; f++) s += hr[f] * s_w[f * 16 + c];
            o[c] = s;
        }
#pragma unroll
        for (int i = 0; i < 4; i++) {
            *reinterpret_cast<float4*>(&out[n * 16 + i * 4]) =
                make_float4(o[4 * i], o[4 * i + 1], o[4 * i + 2], o[4 * i + 3]);
        }
    }
}

// ---------------- launch ----------------
extern "C" void kernel_launch(void* const* d_in, const int* in_sizes, int n_in,
                              void* d_out, int out_size) {
    const float* x     = (const float*)d_in[0];
    const int*   ei    = (const int*)  d_in[1];
    const float* fc0w  = (const float*)d_in[2];
    const float* fc0b  = (const float*)d_in[3];
    const float* fc1w  = (const float*)d_in[4];
    const float* fc1b  = (const float*)d_in[5];
    const float* envw  = (const float*)d_in[6];
    const float* envb  = (const float*)d_in[7];
    const float* convw = (const float*)d_in[8];
    float* out = (float*)d_out;

    const int* row = ei;
    const int* col = ei + EE;

    const int fc0_smem = (64 * 132 + 128 * 64) * (int)sizeof(float);
    cudaFuncSetAttribute(fc0_kernel, cudaFuncAttributeMaxDynamicSharedMemorySize, fc0_smem);
    cudaFuncSetAttribute(conv_mma_kernel, cudaFuncAttributeMaxDynamicSharedMemorySize, CONV_SMEM);

    // edge normalization (constant across layers)
    zero_dn_kernel<<<(NN + 255) / 256, 256>>>();
    deg_kernel<<<(EE + 255) / 256, 256>>>(col);
    dn_kernel<<<(NN + 255) / 256, 256>>>();
    val_kernel<<<(EE + 255) / 256, 256>>>(row, col);

    // pre-packed bf16 hi/lo B fragments
    wpack_kernel<<<48, 256>>>(convw);

    fc0_kernel<<<(NN + 63) / 64, 256, fc0_smem>>>(x, fc0w, fc0b);

    for (int i = 0; i < LL; i++) {
        zero_agg_kernel<<<(NN * HH / 4 + 255) / 256, 256>>>();
        scatter_kernel<<<(EE * 16) / 256, 256>>>(row, col);
        conv_mma_kernel<<<(NN + 127) / 128, 256, CONV_SMEM>>>(
            envw + i * 2 * HH * KK, envb + i * KK, i);
    }

    fc1_kernel<<<(NN + 255) / 256, 256>>>(fc1w, fc1b, out);
}

// round 5
// speedup vs baseline: 2.0872x; 1.1550x over previous
#include <cuda_runtime.h>
#include <cuda_bf16.h>
#include <cstdint>

#define NN 100000
#define DD 128
#define HH 64
#define KK 8
#define LL 3
#define CC 16
#define EE 1600000

// ---------------- device scratch ----------------
__device__ __align__(128) float g_h[NN * HH];
__device__ __align__(128) float g_agg[NN * HH];
__device__ __align__(128) float g_dn[NN];
__device__ __align__(128) int   g_deg[NN];
__device__ __align__(128) int   g_ptr[NN + 1];
__device__ __align__(128) int   g_cur[NN];
__device__ __align__(128) int   g_bsum[128];
__device__ __align__(128) uint2 g_csr[EE];            // (src, val bits)
// pre-packed B fragments: [ (l*8+k)*2 + sel ][kstep*8+ntile][lane] as uint2
__device__ __align__(128) uint2 g_wpack[48 * 2048];

// single dynamic smem symbol shared by all kernels
extern __shared__ unsigned char dyn_smem[];

__device__ __forceinline__ uint16_t bf16_bits(float v) {
    __nv_bfloat16 b = __float2bfloat16(v);
    return *reinterpret_cast<uint16_t*>(&b);
}
__device__ __forceinline__ float bf16_val(float v) {
    return __bfloat162float(__float2bfloat16(v));
}
__device__ __forceinline__ uint32_t pack2(uint16_t lo, uint16_t hi) {
    return (uint32_t)lo | ((uint32_t)hi << 16);
}

// mma.sync m16n8k16 bf16 (row.col), f32 accumulate
__device__ __forceinline__ void hmma(float* d, const uint32_t* a, uint2 b) {
    asm volatile(
        "mma.sync.aligned.m16n8k16.row.col.f32.bf16.bf16.f32 "
        "{%0,%1,%2,%3}, {%4,%5,%6,%7}, {%8,%9}, {%0,%1,%2,%3};"
        : "+f"(d[0]), "+f"(d[1]), "+f"(d[2]), "+f"(d[3])
        : "r"(a[0]), "r"(a[1]), "r"(a[2]), "r"(a[3]), "r"(b.x), "r"(b.y));
}

// ---------------- CSR build kernels ----------------
__global__ void zero_deg_kernel() {
    int i = blockIdx.x * blockDim.x + threadIdx.x;
    if (i < NN) g_deg[i] = 0;
}
__global__ void deg_kernel(const int* __restrict__ col) {
    int e = blockIdx.x * blockDim.x + threadIdx.x;
    if (e < EE) atomicAdd(&g_deg[col[e]], 1);
}
__global__ void dn_kernel() {
    int i = blockIdx.x * blockDim.x + threadIdx.x;
    if (i < NN) {
        int d = g_deg[i];
        g_dn[i] = d > 0 ? rsqrtf((float)d) : 0.f;
    }
}
// per-block exclusive scan of degrees (1024 threads)
__global__ void __launch_bounds__(1024) scan_block_kernel() {
    __shared__ int s[1024];
    int t = threadIdx.x;
    int i = blockIdx.x * 1024 + t;
    int v = (i < NN) ? g_deg[i] : 0;
    s[t] = v;
    __syncthreads();
#pragma unroll
    for (int off = 1; off < 1024; off <<= 1) {
        int x = (t >= off) ? s[t - off] : 0;
        __syncthreads();
        s[t] += x;
        __syncthreads();
    }
    if (i < NN) g_ptr[i] = s[t] - v;  // exclusive within block
    if (t == 1023) g_bsum[blockIdx.x] = s[1023];
}
__global__ void scan_bsum_kernel(int nblocks) {
    if (threadIdx.x == 0 && blockIdx.x == 0) {
        int acc = 0;
        for (int b = 0; b < nblocks; b++) {
            int v = g_bsum[b];
            g_bsum[b] = acc;
            acc += v;
        }
        g_ptr[NN] = acc;
    }
}
__global__ void __launch_bounds__(1024) scan_add_kernel() {
    int i = blockIdx.x * 1024 + threadIdx.x;
    if (i < NN) {
        int p = g_ptr[i] + g_bsum[blockIdx.x];
        g_ptr[i] = p;
        g_cur[i] = p;
    }
}
__global__ void fill_csr_kernel(const int* __restrict__ row, const int* __restrict__ col) {
    int e = blockIdx.x * blockDim.x + threadIdx.x;
    if (e < EE) {
        int c = col[e], r = row[e];
        int p = atomicAdd(&g_cur[c], 1);
        g_csr[p] = make_uint2((unsigned)r, __float_as_uint(g_dn[r] * g_dn[c]));
    }
}

// ---------------- gather: agg[n] = sum_j val_j * h[src_j]  (warp per node) ----------------
__global__ void __launch_bounds__(256) gather_kernel() {
    int n = blockIdx.x * 8 + (threadIdx.x >> 5);
    if (n >= NN) return;
    int lane = threadIdx.x & 31;
    int js = g_ptr[n], je = g_ptr[n + 1];
    const float2* h2 = reinterpret_cast<const float2*>(g_h);
    float2 acc = make_float2(0.f, 0.f);
    int j = js;
    for (; j + 4 <= je; j += 4) {
        uint2 c0 = g_csr[j], c1 = g_csr[j + 1], c2 = g_csr[j + 2], c3 = g_csr[j + 3];
        float2 a0 = h2[c0.x * 32 + lane];
        float2 a1 = h2[c1.x * 32 + lane];
        float2 a2 = h2[c2.x * 32 + lane];
        float2 a3 = h2[c3.x * 32 + lane];
        float v0 = __uint_as_float(c0.y), v1 = __uint_as_float(c1.y);
        float v2 = __uint_as_float(c2.y), v3 = __uint_as_float(c3.y);
        acc.x += v0 * a0.x; acc.y += v0 * a0.y;
        acc.x += v1 * a1.x; acc.y += v1 * a1.y;
        acc.x += v2 * a2.x; acc.y += v2 * a2.y;
        acc.x += v3 * a3.x; acc.y += v3 * a3.y;
    }
    for (; j < je; j++) {
        uint2 c = g_csr[j];
        float2 a = h2[c.x * 32 + lane];
        float v = __uint_as_float(c.y);
        acc.x += v * a.x; acc.y += v * a.y;
    }
    reinterpret_cast<float2*>(g_agg)[n * 32 + lane] = acc;
}

// ---------------- W prepack: bf16 hi/lo split, HMMA B-fragment order ----------------
__global__ void wpack_kernel(const float* __restrict__ cw) {
    int img = blockIdx.x;          // 0..47
    int sel = img & 1;             // 0=hi, 1=lo
    int lk = img >> 1;             // l*8+k
    const float* w = cw + lk * 8192;          // [128 f][64 o]
    uint2* dst = g_wpack + img * 2048;
    for (int i = threadIdx.x; i < 2048; i += 256) {
        int lane = i & 31;
        int nt = (i >> 5) & 7;
        int ks = i >> 8;
        int tig = lane & 3, gid = lane >> 2;
        int n = nt * 8 + gid;
        int k0 = ks * 16 + tig * 2;
        float v0 = w[(k0 + 0) * 64 + n];
        float v1 = w[(k0 + 1) * 64 + n];
        float v2 = w[(k0 + 8) * 64 + n];
        float v3 = w[(k0 + 9) * 64 + n];
        uint16_t h0, h1, h2, h3;
        if (sel == 0) {
            h0 = bf16_bits(v0); h1 = bf16_bits(v1); h2 = bf16_bits(v2); h3 = bf16_bits(v3);
        } else {
            h0 = bf16_bits(v0 - bf16_val(v0));
            h1 = bf16_bits(v1 - bf16_val(v1));
            h2 = bf16_bits(v2 - bf16_val(v2));
            h3 = bf16_bits(v3 - bf16_val(v3));
        }
        dst[i] = make_uint2(pack2(h0, h1), pack2(h2, h3));
    }
}

// ---------------- fc0: h = relu(x @ w + b) ----------------
__global__ void __launch_bounds__(256) fc0_kernel(const float* __restrict__ x,
                                                  const float* __restrict__ w,
                                                  const float* __restrict__ b) {
    float* smf = reinterpret_cast<float*>(dyn_smem);
    float* s_x = smf;               // 64 x 132
    float* s_w = smf + 64 * 132;    // 128 x 64
    int n0 = blockIdx.x * 64;
    int t = threadIdx.x;
    for (int idx = t; idx < 64 * 128; idx += 256) {
        int n = idx >> 7, f = idx & 127;
        int gn = n0 + n;
        s_x[n * 132 + f] = (gn < NN) ? x[gn * 128 + f] : 0.f;
    }
    for (int idx = t; idx < 128 * 64; idx += 256) s_w[idx] = w[idx];
    __syncthreads();

    int ty = t >> 4, tx = t & 15;
    int r0 = ty * 4, c0 = tx * 4;
    float acc[4][4] = {};
#pragma unroll 4
    for (int f = 0; f < 128; f++) {
        float a[4];
#pragma unroll
        for (int i = 0; i < 4; i++) a[i] = s_x[(r0 + i) * 132 + f];
        float4 b4 = *reinterpret_cast<const float4*>(&s_w[f * 64 + c0]);
#pragma unroll
        for (int i = 0; i < 4; i++) {
            acc[i][0] += a[i] * b4.x; acc[i][1] += a[i] * b4.y;
            acc[i][2] += a[i] * b4.z; acc[i][3] += a[i] * b4.w;
        }
    }
    float4 bias = *reinterpret_cast<const float4*>(&b[c0]);
#pragma unroll
    for (int i = 0; i < 4; i++) {
        int gn = n0 + r0 + i;
        if (gn < NN) {
            float4 o;
            o.x = fmaxf(acc[i][0] + bias.x, 0.f);
            o.y = fmaxf(acc[i][1] + bias.y, 0.f);
            o.z = fmaxf(acc[i][2] + bias.z, 0.f);
            o.w = fmaxf(acc[i][3] + bias.w, 0.f);
            *reinterpret_cast<float4*>(&g_h[gn * 64 + c0]) = o;
        }
    }
}

// ---------------- conv layer via mma.sync bf16x3 ----------------
// smem: Ah [128][136] bf16, Al [128][136] bf16, e [128][8] f32, ew 520 f32
#define A_STRIDE 136
#define SM_AH 0
#define SM_AL (128 * A_STRIDE * 2)
#define SM_E  (2 * 128 * A_STRIDE * 2)
#define SM_EW (SM_E + 128 * 8 * 4)
#define CONV_SMEM (SM_EW + 520 * 4)

__global__ void __launch_bounds__(256, 1) conv_mma_kernel(const float* __restrict__ ew,
                                                          const float* __restrict__ eb,
                                                          int layer) {
    unsigned char* smb = dyn_smem;
    uint16_t* Ah = reinterpret_cast<uint16_t*>(smb + SM_AH);
    uint16_t* Al = reinterpret_cast<uint16_t*>(smb + SM_AL);
    float* s_e = reinterpret_cast<float*>(smb + SM_E);
    float* s_ew = reinterpret_cast<float*>(smb + SM_EW);

    int t = threadIdx.x;
    int wid = t >> 5, lane = t & 31;
    int tig = lane & 3, gid = lane >> 2;
    int n0 = blockIdx.x * 128;

    // env weights + bias into smem
    for (int i = t; i < 520; i += 256) s_ew[i] = (i < 512) ? ew[i] : eb[i - 512];

    // ---- build A tile (bf16 hi/lo split) ----
    const float4* agg4 = reinterpret_cast<const float4*>(g_agg);
    const float4* h4 = reinterpret_cast<const float4*>(g_h);
    for (int idx = t; idx < 4096; idx += 256) {
        int r = idx >> 5, j = idx & 31;        // j: float4 index within row (0..31)
        int gn = n0 + r;
        float4 v = make_float4(0.f, 0.f, 0.f, 0.f);
        if (gn < NN) v = (j < 16) ? agg4[gn * 16 + j] : h4[gn * 16 + (j - 16)];
        uint16_t hx = bf16_bits(v.x), hy = bf16_bits(v.y);
        uint16_t hz = bf16_bits(v.z), hw = bf16_bits(v.w);
        uint16_t lx = bf16_bits(v.x - bf16_val(v.x));
        uint16_t ly = bf16_bits(v.y - bf16_val(v.y));
        uint16_t lz = bf16_bits(v.z - bf16_val(v.z));
        uint16_t lw = bf16_bits(v.w - bf16_val(v.w));
        *reinterpret_cast<uint2*>(&Ah[r * A_STRIDE + j * 4]) = make_uint2(pack2(hx, hy), pack2(hz, hw));
        *reinterpret_cast<uint2*>(&Al[r * A_STRIDE + j * 4]) = make_uint2(pack2(lx, ly), pack2(lz, lw));
    }
    __syncthreads();

    // ---- A fragments into registers (held across all heads) ----
    uint32_t ah[8][4], al[8][4];
    int fr0 = wid * 16 + gid;
#pragma unroll
    for (int s = 0; s < 8; s++) {
        int kc = s * 16 + tig * 2;
        ah[s][0] = *reinterpret_cast<const uint32_t*>(&Ah[fr0 * A_STRIDE + kc]);
        ah[s][1] = *reinterpret_cast<const uint32_t*>(&Ah[(fr0 + 8) * A_STRIDE + kc]);
        ah[s][2] = *reinterpret_cast<const uint32_t*>(&Ah[fr0 * A_STRIDE + kc + 8]);
        ah[s][3] = *reinterpret_cast<const uint32_t*>(&Ah[(fr0 + 8) * A_STRIDE + kc + 8]);
        al[s][0] = *reinterpret_cast<const uint32_t*>(&Al[fr0 * A_STRIDE + kc]);
        al[s][1] = *reinterpret_cast<const uint32_t*>(&Al[(fr0 + 8) * A_STRIDE + kc]);
        al[s][2] = *reinterpret_cast<const uint32_t*>(&Al[fr0 * A_STRIDE + kc + 8]);
        al[s][3] = *reinterpret_cast<const uint32_t*>(&Al[(fr0 + 8) * A_STRIDE + kc + 8]);
    }

    // ---- gating (threads 0..127, one node each), fp32 ----
    if (t < 128) {
        int gn = n0 + t;
        float hrow[64];
        if (gn < NN) {
#pragma unroll
            for (int i = 0; i < 16; i++) {
                float4 v = h4[gn * 16 + i];
                hrow[4 * i] = v.x; hrow[4 * i + 1] = v.y;
                hrow[4 * i + 2] = v.z; hrow[4 * i + 3] = v.w;
            }
        } else {
#pragma unroll
            for (int i = 0; i < 64; i++) hrow[i] = 0.f;
        }
        float lg[8];
#pragma unroll
        for (int k = 0; k < 8; k++) lg[k] = s_ew[512 + k];
#pragma unroll 8
        for (int f = 0; f < 64; f++) {
            float hv = hrow[f];
            float4 w0 = *reinterpret_cast<const float4*>(&s_ew[f * 8]);
            float4 w1 = *reinterpret_cast<const float4*>(&s_ew[f * 8 + 4]);
            lg[0] += hv * w0.x; lg[1] += hv * w0.y; lg[2] += hv * w0.z; lg[3] += hv * w0.w;
            lg[4] += hv * w1.x; lg[5] += hv * w1.y; lg[6] += hv * w1.z; lg[7] += hv * w1.w;
        }
        float m = -1e30f;
#pragma unroll
        for (int k = 0; k < 8; k++) m = fmaxf(m, lg[k]);
        float sum = 0.f;
#pragma unroll
        for (int k = 0; k < 8; k++) { lg[k] = expf(lg[k] - m); sum += lg[k]; }
        float inv = 1.f / sum;
#pragma unroll
        for (int k = 0; k < 8; k++) {
            float pi = lg[k] * inv;
            s_e[t * 8 + k] = (pi > 0.1f) ? pi : 0.f;
        }
    }
    __syncthreads();

    // ---- main MMA loop over 8 heads ----
    float acc[8][4];
#pragma unroll
    for (int nt = 0; nt < 8; nt++)
#pragma unroll
        for (int i = 0; i < 4; i++) acc[nt][i] = 0.f;

    const uint2* wp = g_wpack + (layer * 8) * 2 * 2048;

#pragma unroll 1
    for (int k = 0; k < 8; k++) {
        const uint2* bh = wp + (k * 2 + 0) * 2048;
        const uint2* bl = wp + (k * 2 + 1) * 2048;
        float acck[8][4];
#pragma unroll
        for (int nt = 0; nt < 8; nt++)
#pragma unroll
            for (int i = 0; i < 4; i++) acck[nt][i] = 0.f;

        // pass 1: (Ah + Al) x Bh
#pragma unroll
        for (int s = 0; s < 8; s++) {
            uint2 b[8];
#pragma unroll
            for (int nt = 0; nt < 8; nt++) b[nt] = bh[(s * 8 + nt) * 32 + lane];
#pragma unroll
            for (int nt = 0; nt < 8; nt++) hmma(acck[nt], ah[s], b[nt]);
#pragma unroll
            for (int nt = 0; nt < 8; nt++) hmma(acck[nt], al[s], b[nt]);
        }
        // pass 2: Ah x Bl
#pragma unroll
        for (int s = 0; s < 8; s++) {
            uint2 b[8];
#pragma unroll
            for (int nt = 0; nt < 8; nt++) b[nt] = bl[(s * 8 + nt) * 32 + lane];
#pragma unroll
            for (int nt = 0; nt < 8; nt++) hmma(acck[nt], ah[s], b[nt]);
        }

        float e0 = s_e[(wid * 16 + gid) * 8 + k];
        float e1 = s_e[(wid * 16 + gid + 8) * 8 + k];
#pragma unroll
        for (int nt = 0; nt < 8; nt++) {
            acc[nt][0] += e0 * acck[nt][0];
            acc[nt][1] += e0 * acck[nt][1];
            acc[nt][2] += e1 * acck[nt][2];
            acc[nt][3] += e1 * acck[nt][3];
        }
    }

    // ---- epilogue: h = relu(acc + h), in-place ----
    int gn0 = n0 + wid * 16 + gid;
    int gn1 = gn0 + 8;
#pragma unroll
    for (int nt = 0; nt < 8; nt++) {
        int c = nt * 8 + tig * 2;
        if (gn0 < NN) {
            float2 hv = *reinterpret_cast<const float2*>(&g_h[gn0 * 64 + c]);
            float2 o;
            o.x = fmaxf(acc[nt][0] + hv.x, 0.f);
            o.y = fmaxf(acc[nt][1] + hv.y, 0.f);
            *reinterpret_cast<float2*>(&g_h[gn0 * 64 + c]) = o;
        }
        if (gn1 < NN) {
            float2 hv = *reinterpret_cast<const float2*>(&g_h[gn1 * 64 + c]);
            float2 o;
            o.x = fmaxf(acc[nt][2] + hv.x, 0.f);
            o.y = fmaxf(acc[nt][3] + hv.y, 0.f);
            *reinterpret_cast<float2*>(&g_h[gn1 * 64 + c]) = o;
        }
    }
}

// ---------------- fc1 ----------------
__global__ void __launch_bounds__(256) fc1_kernel(const float* __restrict__ w,
                                                  const float* __restrict__ b,
                                                  float* __restrict__ out) {
    __shared__ float s_w[64 * 16];
    __shared__ float s_b[16];
    int t = threadIdx.x;
    for (int idx = t; idx < 64 * 16; idx += 256) s_w[idx] = w[idx];
    if (t < 16) s_b[t] = b[t];
    __syncthreads();
    int n = blockIdx.x * 256 + t;
    if (n < NN) {
        float hr[64];
#pragma unroll
        for (int i = 0; i < 16; i++) {
            float4 v = *reinterpret_cast<const float4*>(&g_h[n * 64 + i * 4]);
            hr[4 * i] = v.x; hr[4 * i + 1] = v.y; hr[4 * i + 2] = v.z; hr[4 * i + 3] = v.w;
        }
        float o[16];
#pragma unroll
        for (int c = 0; c < 16; c++) {
            float s = s_b[c];
#pragma unroll
            for (int f = 0; f < 64; f++) s += hr[f] * s_w[f * 16 + c];
            o[c] = s;
        }
#pragma unroll
        for (int i = 0; i < 4; i++) {
            *reinterpret_cast<float4*>(&out[n * 16 + i * 4]) =
                make_float4(o[4 * i], o[4 * i + 1], o[4 * i + 2], o[4 * i + 3]);
        }
    }
}

// ---------------- launch ----------------
extern "C" void kernel_launch(void* const* d_in, const int* in_sizes, int n_in,
                              void* d_out, int out_size) {
    const float* x     = (const float*)d_in[0];
    const int*   ei    = (const int*)  d_in[1];
    const float* fc0w  = (const float*)d_in[2];
    const float* fc0b  = (const float*)d_in[3];
    const float* fc1w  = (const float*)d_in[4];
    const float* fc1b  = (const float*)d_in[5];
    const float* envw  = (const float*)d_in[6];
    const float* envb  = (const float*)d_in[7];
    const float* convw = (const float*)d_in[8];
    float* out = (float*)d_out;

    const int* row = ei;
    const int* col = ei + EE;

    const int fc0_smem = (64 * 132 + 128 * 64) * (int)sizeof(float);
    cudaFuncSetAttribute(fc0_kernel, cudaFuncAttributeMaxDynamicSharedMemorySize, fc0_smem);
    cudaFuncSetAttribute(conv_mma_kernel, cudaFuncAttributeMaxDynamicSharedMemorySize, CONV_SMEM);

    const int nscan = (NN + 1023) / 1024;   // 98

    // CSR build (edges fixed across layers)
    zero_deg_kernel<<<(NN + 255) / 256, 256>>>();
    deg_kernel<<<(EE + 255) / 256, 256>>>(col);
    dn_kernel<<<(NN + 255) / 256, 256>>>();
    scan_block_kernel<<<nscan, 1024>>>();
    scan_bsum_kernel<<<1, 32>>>(nscan);
    scan_add_kernel<<<nscan, 1024>>>();
    fill_csr_kernel<<<(EE + 255) / 256, 256>>>(row, col);

    // pre-packed bf16 hi/lo B fragments
    wpack_kernel<<<48, 256>>>(convw);

    fc0_kernel<<<(NN + 63) / 64, 256, fc0_smem>>>(x, fc0w, fc0b);

    for (int i = 0; i < LL; i++) {
        gather_kernel<<<(NN + 7) / 8, 256>>>();
        conv_mma_kernel<<<(NN + 127) / 128, 256, CONV_SMEM>>>(
            envw + i * 2 * HH * KK, envb + i * KK, i);
    }

    fc1_kernel<<<(NN + 255) / 256, 256>>>(fc1w, fc1b, out);
}